// round 17
// baseline (speedup 1.0000x reference)
#include <cuda_runtime.h>
#include <cuda_fp16.h>
#include <cstdint>
#include <cmath>

#define NTOK 8192
#define HDIM 2048
#define IDIM 8192
#define KSEL 2048
#define DELTA 1.5e-3f
#define BCAP 160
#define GSTR (2 * IDIM)          // fused gate|v row stride

__device__ float g_gv [(size_t)NTOK * GSTR];        // [N, 2I]: gate | v
__device__ __half g_xh [(size_t)NTOK * HDIM];       // x  h-plane
__device__ __half g_w1 [2 * (size_t)IDIM * HDIM];   // [Wg_h ; Wu_h]
__device__ __half g_wd [(size_t)HDIM * IDIM];       // Wd h-plane
__device__ __half g_ah [(size_t)NTOK * IDIM];       // activation h-plane

__device__ __forceinline__ uint32_t smem_u32(const void* p) {
    uint32_t a;
    asm("{ .reg .u64 t; cvta.to.shared.u64 t, %1; cvt.u32.u64 %0, t; }" : "=r"(a) : "l"(p));
    return a;
}
#define MBAR_INIT(a, c) asm volatile("mbarrier.init.shared.b64 [%0], %1;" :: "r"(a), "r"(c) : "memory")
#define MBAR_EXPECT_TX(a, b) \
    asm volatile("mbarrier.arrive.expect_tx.shared.b64 _, [%0], %1;" :: "r"(a), "r"(b) : "memory")
#define MBAR_WAIT(a, ph) do { uint32_t _m=(a), _p=(ph), _d;                                          \
    asm volatile("{ .reg .pred p; mbarrier.try_wait.parity.acquire.cta.shared::cta.b64 p,[%1],%2; "  \
                 "selp.b32 %0,1,0,p; }" : "=r"(_d) : "r"(_m), "r"(_p) : "memory");                   \
    if (!_d) { asm volatile("{ .reg .pred P; LW_%=: "                                                \
        "mbarrier.try_wait.parity.acquire.cta.shared::cta.b64 P,[%0],%1,0x989680; "                  \
        "@P bra.uni LD_%=; bra.uni LW_%=; LD_%=: }" :: "r"(_m), "r"(_p) : "memory"); } } while (0)
#define BULK256(d, s, mbar) \
    asm volatile("cp.async.bulk.shared::cta.global.mbarrier::complete_tx::bytes [%0], [%1], 256, [%2];" \
                 :: "r"(d), "l"(s), "r"(mbar) : "memory")
#define LDM4(r0, r1, r2, r3, a) \
    asm volatile("ldmatrix.sync.aligned.m8n8.x4.shared.b16 {%0,%1,%2,%3}, [%4];" \
                 : "=r"(r0), "=r"(r1), "=r"(r2), "=r"(r3) : "r"(a))
#define MMA16816(c0, c1, c2, c3, a0, a1, a2, a3, b0, b1) \
    asm volatile("mma.sync.aligned.m16n8k16.row.col.f32.f16.f16.f32 " \
                 "{%0,%1,%2,%3},{%4,%5,%6,%7},{%8,%9},{%0,%1,%2,%3};" \
                 : "+f"(c0), "+f"(c1), "+f"(c2), "+f"(c3) \
                 : "r"(a0), "r"(a1), "r"(a2), "r"(a3), "r"(b0), "r"(b1))

__device__ __forceinline__ unsigned f2k(float f) {
    unsigned b = __float_as_uint(f);
    return (b & 0x80000000u) ? ~b : (b | 0x80000000u);
}
__device__ __forceinline__ float k2f(unsigned u) {
    unsigned b = (u & 0x80000000u) ? (u & 0x7FFFFFFFu) : ~u;
    return __uint_as_float(b);
}

// ---------------------------------------------------------------------------
// Plain fp16 GEMM, cp.async.bulk edition.
//   C[m][n] = A[m,:] . B[n,:]   (A [M,K], B [N,K] fp16 row-major; C [M,N] f32)
// CTA 128x256, 256 thr, warp tile 64x64. K-chunk 128 (256B per row).
// SMEM: per stage, 384 rows (128 A + 256 B) at padded stride 272B
// (row r banks start at (r*4) mod 32 -> 8-row LDSM groups conflict-free,
//  no swizzle needed; bulk copies are row-contiguous).
// 2 stages + per-stage mbarrier (expect_tx 98304 bytes).
// ---------------------------------------------------------------------------
#define BM 128
#define BN 256
#define RSTR 272u
#define STAGE (384 * 272)        // 104448
#define TXBYTES 98304u           // 384 rows * 256B actual payload
#define SMEMSZ (2 * STAGE + 16)

__device__ __forceinline__ void bload(uint32_t st, uint32_t mbar,
    const __half* __restrict__ A, const __half* __restrict__ B,
    int bm, int bn, int K, int k0, int tid)
{
    if (tid == 0) MBAR_EXPECT_TX(mbar, TXBYTES);
    for (int r = tid; r < 384; r += 256) {
        const __half* src = (r < 128)
            ? A + (size_t)(bm + r) * K + k0
            : B + (size_t)(bn + r - 128) * K + k0;
        BULK256(st + (uint32_t)r * RSTR, src, mbar);
    }
}

__global__ __launch_bounds__(256, 1)
void hgemm(const __half* __restrict__ A, const __half* __restrict__ B,
           float* __restrict__ C, int N, int K)
{
    extern __shared__ char smem[];
    const uint32_t sb = smem_u32(smem);
    const uint32_t mb = sb + 2 * STAGE;      // two 8B mbarriers
    const int tid = threadIdx.x, wid = tid >> 5, lane = tid & 31;
    const int bm = blockIdx.y * BM, bn = blockIdx.x * BN;
    const int wm = (wid >> 2) * 64, wn = (wid & 3) * 64;
    const int CH = K >> 7;                   // 128-wide chunks

    if (tid == 0) { MBAR_INIT(mb, 1); MBAR_INIT(mb + 8, 1); }
    __syncthreads();

    float c[4][8][4];
#pragma unroll
    for (int i = 0; i < 4; i++)
#pragma unroll
        for (int j = 0; j < 8; j++)
#pragma unroll
            for (int q = 0; q < 4; q++) c[i][j][q] = 0.f;

    bload(sb, mb, A, B, bm, bn, K, 0, tid);  // prologue: stage 0

    const int a_mrow = lane & 15;
    const int a_kc   = lane >> 4;
    const int b_nrow = (lane & 7) + ((lane >> 4) << 3);
    const int b_kc   = (lane >> 3) & 1;

    for (int t = 0; t < CH; t++) {
        const uint32_t st = sb + (uint32_t)(t & 1) * STAGE;
        MBAR_WAIT(mb + 8u * (t & 1), (t >> 1) & 1);
        __syncthreads();
        if (t + 1 < CH)
            bload(sb + (uint32_t)((t + 1) & 1) * STAGE, mb + 8u * ((t + 1) & 1),
                  A, B, bm, bn, K, (t + 1) * 128, tid);

        const uint32_t abase = st;
        const uint32_t bbase = st + 128u * RSTR;
#pragma unroll
        for (int kk = 0; kk < 8; kk++) {
            uint32_t a[4][4], b[4][4];
#pragma unroll
            for (int mt = 0; mt < 4; mt++) {
                int r = wm + mt * 16 + a_mrow;
                int ch = kk * 2 + a_kc;
                LDM4(a[mt][0], a[mt][1], a[mt][2], a[mt][3],
                     abase + (uint32_t)r * RSTR + (uint32_t)ch * 16u);
            }
#pragma unroll
            for (int nt = 0; nt < 4; nt++) {
                int r = wn + nt * 16 + b_nrow;
                int ch = kk * 2 + b_kc;
                LDM4(b[nt][0], b[nt][1], b[nt][2], b[nt][3],
                     bbase + (uint32_t)r * RSTR + (uint32_t)ch * 16u);
            }
#pragma unroll
            for (int mt = 0; mt < 4; mt++)
#pragma unroll
                for (int j = 0; j < 8; j++)
                    MMA16816(c[mt][j][0], c[mt][j][1], c[mt][j][2], c[mt][j][3],
                             a[mt][0], a[mt][1], a[mt][2], a[mt][3],
                             b[j >> 1][(j & 1) * 2], b[j >> 1][(j & 1) * 2 + 1]);
        }
    }

#pragma unroll
    for (int mt = 0; mt < 4; mt++) {
        int row = bm + wm + mt * 16 + (lane >> 2);
#pragma unroll
        for (int j = 0; j < 8; j++) {
            int col = bn + wn + j * 8 + (lane & 3) * 2;
            *(float2*)(C + (size_t)row * N + col)       = make_float2(c[mt][j][0], c[mt][j][1]);
            *(float2*)(C + (size_t)(row + 8) * N + col) = make_float2(c[mt][j][2], c[mt][j][3]);
        }
    }
}

// ---------------------------------------------------------------------------
__global__ void split1h(const float4* __restrict__ a, __half* __restrict__ o, size_t n)
{
    const size_t n4 = n >> 2;
    size_t i = (size_t)blockIdx.x * blockDim.x + threadIdx.x;
    for (; i < n4; i += (size_t)gridDim.x * blockDim.x) {
        float4 x = a[i];
        *(__half2*)(o + 4 * i)     = __halves2half2(__float2half_rn(x.x), __float2half_rn(x.y));
        *(__half2*)(o + 4 * i + 2) = __halves2half2(__float2half_rn(x.z), __float2half_rn(x.w));
    }
}

// ---------------------------------------------------------------------------
// Top-K with exact boundary resolution (staged cooperative recompute of band
// gates in the reference's sequential-k fp32 order).
// ---------------------------------------------------------------------------
#define GRP 8
#define CHK 256

__global__ __launch_bounds__(256)
void topk_kernel(const float* __restrict__ gv,
                 const float* __restrict__ x, const float* __restrict__ Wg,
                 __half* __restrict__ ah)
{
    __shared__ unsigned s_u[IDIM];
    __shared__ float    s_buf[GRP][CHK + 4];
    __shared__ float    s_xc[CHK];
    __shared__ int      hist[256];
    __shared__ int      s_bidx[BCAP];
    __shared__ float    s_bg[BCAP];
    __shared__ unsigned char s_bsel[BCAP];
    __shared__ unsigned s_prefix;
    __shared__ int s_kk, s_na, s_nb;

    const int row = blockIdx.x, tid = threadIdx.x;
    const float* grow = gv + (size_t)row * GSTR;
    const float* vrow = grow + IDIM;
    const float* xrow = x + (size_t)row * HDIM;

    for (int i = tid * 4; i < IDIM; i += 1024) {
        float4 g4 = *(const float4*)(grow + i);
        s_u[i]     = f2k(g4.x); s_u[i + 1] = f2k(g4.y);
        s_u[i + 2] = f2k(g4.z); s_u[i + 3] = f2k(g4.w);
    }
    if (tid == 0) { s_prefix = 0u; s_kk = KSEL; s_na = 0; s_nb = 0; }
    __syncthreads();

#pragma unroll
    for (int pass = 0; pass < 4; pass++) {
        const int shift = 24 - 8 * pass;
        hist[tid] = 0;
        __syncthreads();
        const unsigned prefix = s_prefix;
        const unsigned himask = (pass == 0) ? 0u : (0xFFFFFFFFu << (shift + 8));
        for (int i = tid; i < IDIM; i += 256) {
            unsigned u = s_u[i];
            if ((u & himask) == prefix) atomicAdd(&hist[(u >> shift) & 255], 1);
        }
        __syncthreads();
        if (tid == 0) {
            int kk = s_kk, cum = 0, b = 0;
            for (int q = 255; q >= 0; q--) { cum += hist[q]; if (cum >= kk) { b = q; break; } }
            s_kk = kk - (cum - hist[b]);
            s_prefix = prefix | ((unsigned)b << shift);
        }
        __syncthreads();
    }
    const unsigned t = s_prefix;
    const float gt = k2f(t);
    const unsigned hik = f2k(gt + DELTA);
    const unsigned lok = f2k(gt - DELTA);
    __syncthreads();

    for (int i = tid; i < IDIM; i += 256) {
        unsigned u = s_u[i];
        if (u > hik) atomicAdd(&s_na, 1);
        else if (u >= lok) {
            int p = atomicAdd(&s_nb, 1);
            if (p < BCAP) s_bidx[p] = i;
        }
    }
    __syncthreads();
    const int nb = s_nb;
    const int nb_c = nb < BCAP ? nb : BCAP;
    const bool ovf = nb > BCAP;
    const int quota = KSEL - s_na;

    if (!ovf) {
        for (int g0 = 0; g0 < nb_c; g0 += GRP) {
            const int ng = min(GRP, nb_c - g0);
            float accR = 0.f;
            for (int c0 = 0; c0 < HDIM; c0 += CHK) {
                if (tid < CHK / 4)
                    *(float4*)(s_xc + tid * 4) = *(const float4*)(xrow + c0 + tid * 4);
#pragma unroll
                for (int q = 0; q < (GRP * CHK / 4) / 256; q++) {
                    int idx = tid + q * 256;
                    int e = idx / (CHK / 4);
                    int f = idx % (CHK / 4);
                    if (e < ng)
                        *(float4*)(&s_buf[e][f * 4]) =
                            *(const float4*)(Wg + (size_t)s_bidx[g0 + e] * HDIM + c0 + f * 4);
                }
                __syncthreads();
                if (tid < ng) {
                    const float* bw = s_buf[tid];
#pragma unroll 8
                    for (int kk = 0; kk < CHK; kk++)
                        accR = fmaf(s_xc[kk], bw[kk], accR);
                }
                __syncthreads();
            }
            if (tid < ng) s_bg[g0 + tid] = accR;
        }
        __syncthreads();
        if (tid < nb_c) {
            const float gi = s_bg[tid];
            const int ii = s_bidx[tid];
            int r = 0;
            for (int j = 0; j < nb_c; j++) {
                float gj = s_bg[j];
                if (gj > gi || (gj == gi && s_bidx[j] < ii)) r++;
            }
            s_bsel[tid] = (r < quota) ? 1 : 0;
        }
        __syncthreads();
    }

    for (int i = tid * 4; i < IDIM; i += 1024) {
        float4 v4 = *(const float4*)(vrow + i);
        __half hs[4];
#pragma unroll
        for (int q = 0; q < 4; q++) {
            const unsigned u = s_u[i + q];
            float o = 0.f;
            if (u > hik) {
                float g = k2f(u);
                o = (g / (1.f + expf(-g))) * ((const float*)&v4)[q];
            } else if (u >= lok) {
                if (!ovf) {
                    for (int j = 0; j < nb_c; j++)
                        if (s_bidx[j] == i + q) {
                            if (s_bsel[j]) {
                                float g = s_bg[j];
                                o = (g / (1.f + expf(-g))) * ((const float*)&v4)[q];
                            }
                            break;
                        }
                } else if (u >= t) {
                    float g = k2f(u);
                    o = (g / (1.f + expf(-g))) * ((const float*)&v4)[q];
                }
            }
            hs[q] = __float2half_rn(o);
        }
        const size_t idx = (size_t)row * IDIM + i;
        *(__half2*)(ah + idx)     = __halves2half2(hs[0], hs[1]);
        *(__half2*)(ah + idx + 2) = __halves2half2(hs[2], hs[3]);
    }
}

// ---------------------------------------------------------------------------
extern "C" void kernel_launch(void* const* d_in, const int* in_sizes, int n_in,
                              void* d_out, int out_size)
{
    const float* x  = (const float*)d_in[0];
    const float* Wg = (const float*)d_in[1];
    const float* Wu = (const float*)d_in[2];
    const float* Wd = (const float*)d_in[3];
    float* out = (float*)d_out;

    float* gv;
    __half *xh, *w1, *wd, *ah;
    cudaGetSymbolAddress((void**)&gv, g_gv);
    cudaGetSymbolAddress((void**)&xh, g_xh);
    cudaGetSymbolAddress((void**)&w1, g_w1);
    cudaGetSymbolAddress((void**)&wd, g_wd);
    cudaGetSymbolAddress((void**)&ah, g_ah);

    const size_t nx = (size_t)NTOK * HDIM;
    const size_t nw = (size_t)IDIM * HDIM;

    cudaFuncSetAttribute(hgemm, cudaFuncAttributeMaxDynamicSharedMemorySize, SMEMSZ);

    split1h<<<2048, 256>>>((const float4*)x,  xh, nx);
    split1h<<<2048, 256>>>((const float4*)Wg, w1, nw);
    split1h<<<2048, 256>>>((const float4*)Wu, w1 + nw, nw);
    split1h<<<2048, 256>>>((const float4*)Wd, wd, nw);

    // Fused [gate|v] = x @ [Wg;Wu]^T : M=8192, N=16384, K=2048
    hgemm<<<dim3(GSTR / BN, NTOK / BM), 256, SMEMSZ>>>(xh, w1, gv, GSTR, HDIM);
    // exact-boundary top-k + silu*v -> fp16 activation
    topk_kernel<<<NTOK, 256>>>(gv, x, Wg, ah);
    // out = act @ Wd^T : M=8192, N=2048, K=8192
    hgemm<<<dim3(HDIM / BN, NTOK / BM), 256, SMEMSZ>>>(ah, wd, out, HDIM, IDIM);
}